// round 1
// baseline (speedup 1.0000x reference)
#include <cuda_runtime.h>

#define Bz   4
#define Sz   1024
#define DINz 1024
#define HDz  64
#define Ez   8
#define NHz  4
#define NCOLz 2048          // HD*E*NH
#define BEHz  128           // B*E*NH

// Scratch (device globals: allocation-free rule)
__device__ float g_qt[BEHz * Sz * HDz];          // [beh][i][d]   32 MB
__device__ float g_kt[BEHz * Sz * HDz];          // [beh][k][d]   32 MB
__device__ float g_p [BEHz * Sz * Sz];           // [beh][i][k]   512 MB, exp(S/8)
__device__ float g_z [BEHz * Sz];                // row sums Z_i
__device__ float g_cs[BEHz * 2 * Sz];            // partial column sums

// ---------------------------------------------------------------------------
// Kernel 1: C = x(4096x1024) @ W(1024x2048) + bias, scattered to [beh][i][d]
// Classic 128x128x8 fp32 sgemm, 256 threads, 8x8 micro-tile.
// ---------------------------------------------------------------------------
__global__ __launch_bounds__(256)
void gemm_qk_kernel(const float* __restrict__ X, const float* __restrict__ W,
                    const float* __restrict__ bias, int which)
{
    float* __restrict__ out = which ? g_kt : g_qt;
    __shared__ float As[8][128];   // [k][m]
    __shared__ float Bs[8][128];   // [k][n]

    const int bm  = blockIdx.y * 128;
    const int bn  = blockIdx.x * 128;
    const int tid = threadIdx.x;
    const int tx  = tid & 15;
    const int ty  = tid >> 4;
    const int arow = tid >> 1;
    const int acol = (tid & 1) * 4;
    const int brow = tid >> 5;
    const int bcol = (tid & 31) * 4;

    float acc[8][8];
#pragma unroll
    for (int i = 0; i < 8; i++)
#pragma unroll
        for (int j = 0; j < 8; j++) acc[i][j] = 0.f;

    for (int k0 = 0; k0 < DINz; k0 += 8) {
        float4 a = *(const float4*)(X + (long long)(bm + arow) * DINz + k0 + acol);
        As[acol + 0][arow] = a.x; As[acol + 1][arow] = a.y;
        As[acol + 2][arow] = a.z; As[acol + 3][arow] = a.w;
        *(float4*)&Bs[brow][bcol] =
            *(const float4*)(W + (long long)(k0 + brow) * NCOLz + bn + bcol);
        __syncthreads();
#pragma unroll
        for (int kk = 0; kk < 8; kk++) {
            float4 ra0 = *(const float4*)&As[kk][ty * 8];
            float4 ra1 = *(const float4*)&As[kk][ty * 8 + 4];
            float4 rb0 = *(const float4*)&Bs[kk][tx * 8];
            float4 rb1 = *(const float4*)&Bs[kk][tx * 8 + 4];
            float ra[8] = {ra0.x, ra0.y, ra0.z, ra0.w, ra1.x, ra1.y, ra1.z, ra1.w};
            float rb[8] = {rb0.x, rb0.y, rb0.z, rb0.w, rb1.x, rb1.y, rb1.z, rb1.w};
#pragma unroll
            for (int i = 0; i < 8; i++)
#pragma unroll
                for (int j = 0; j < 8; j++)
                    acc[i][j] = fmaf(ra[i], rb[j], acc[i][j]);
        }
        __syncthreads();
    }

    // Epilogue: bias add + scatter to [beh][i][d]; col = d*32 + e*4 + h
#pragma unroll
    for (int i = 0; i < 8; i++) {
        int row = bm + ty * 8 + i;
        int bb = row >> 10, si = row & 1023;
#pragma unroll
        for (int j = 0; j < 8; j++) {
            int col = bn + tx * 8 + j;
            float v = acc[i][j] + bias[col];
            int d = col >> 5, eh = col & 31;
            out[((((bb << 5) | eh) * Sz + si) << 6) + d] = v;
        }
    }
}

// ---------------------------------------------------------------------------
// Kernel 2: per (beh, 128-row chunk): S = Q K^T / 8 over d=64,
// P = exp(S) stored to g_p, Z_i row sums stored to g_z.
// Tile 128i x 128k, 256 threads, 8x8 micro-tile (interleaved: i=ty+16*ii,
// k=tx+16*kk -> conflict-free padded smem reads).
// ---------------------------------------------------------------------------
#define SMEM_B_BYTES (2 * 128 * 65 * 4)   // 66560

__global__ __launch_bounds__(256)
void attn_score_kernel()
{
    extern __shared__ float sm[];
    float (*Qs)[65] = (float(*)[65])sm;              // [i][d], pad->bank (i+d)%32
    float (*Ks)[65] = (float(*)[65])(sm + 128 * 65); // [k][d]

    const int beh = blockIdx.x;
    const int ic  = blockIdx.y;            // 128-row i chunk (0..7)
    const int tid = threadIdx.x;
    const int tx  = tid & 15;
    const int ty  = tid >> 4;
    const int lr  = tid >> 6;              // load row-group 0..3
    const int ld  = tid & 63;              // load d

    const float* qbase = g_qt + ((long long)beh * Sz + ic * 128) * HDz;
    const float* kbase = g_kt + (long long)beh * Sz * HDz;

#pragma unroll
    for (int r = 0; r < 128; r += 4)
        Qs[r + lr][ld] = qbase[(r + lr) * HDz + ld];

    float zacc[8];
#pragma unroll
    for (int ii = 0; ii < 8; ii++) zacc[ii] = 0.f;

    float* prow = g_p + ((long long)beh * Sz + ic * 128) * Sz;

    for (int kc = 0; kc < 8; kc++) {
        __syncthreads();                       // prev compute done (covers Qs 1st iter)
#pragma unroll
        for (int r = 0; r < 128; r += 4)
            Ks[r + lr][ld] = kbase[(kc * 128 + r + lr) * HDz + ld];
        __syncthreads();

        float acc[8][8];
#pragma unroll
        for (int ii = 0; ii < 8; ii++)
#pragma unroll
            for (int kk = 0; kk < 8; kk++) acc[ii][kk] = 0.f;

#pragma unroll 8
        for (int d = 0; d < 64; d++) {
            float ra[8], rb[8];
#pragma unroll
            for (int ii = 0; ii < 8; ii++) ra[ii] = Qs[ty + 16 * ii][d];
#pragma unroll
            for (int kk = 0; kk < 8; kk++) rb[kk] = Ks[tx + 16 * kk][d];
#pragma unroll
            for (int ii = 0; ii < 8; ii++)
#pragma unroll
                for (int kk = 0; kk < 8; kk++)
                    acc[ii][kk] = fmaf(ra[ii], rb[kk], acc[ii][kk]);
        }

        // fused epilogue: exp(S/8), accumulate Z, store P
#pragma unroll
        for (int ii = 0; ii < 8; ii++) {
            float* pr = prow + (long long)(ty + 16 * ii) * Sz + kc * 128;
#pragma unroll
            for (int kk = 0; kk < 8; kk++) {
                float pv = __expf(acc[ii][kk] * 0.125f);
                zacc[ii] += pv;
                pr[tx + 16 * kk] = pv;
            }
        }
    }

    // Z: reduce the 16 tx-partials per row within each half-warp
#pragma unroll
    for (int ii = 0; ii < 8; ii++) {
        float z = zacc[ii];
        z += __shfl_xor_sync(0xFFFFFFFFu, z, 1);
        z += __shfl_xor_sync(0xFFFFFFFFu, z, 2);
        z += __shfl_xor_sync(0xFFFFFFFFu, z, 4);
        z += __shfl_xor_sync(0xFFFFFFFFu, z, 8);
        if (tx == 0)
            g_z[beh * Sz + ic * 128 + ty + 16 * ii] = z;
    }
}

// ---------------------------------------------------------------------------
// Kernel 3: column sums of P weighted by 1/Z_i (memory-bound).
// Block = (beh, half); thread = one column k; 512 rows each.
// ---------------------------------------------------------------------------
__global__ __launch_bounds__(1024)
void attn_colsum_kernel()
{
    const int beh  = blockIdx.x;
    const int half = blockIdx.y;
    const int k    = threadIdx.x;
    __shared__ float rz[512];
    if (k < 512) rz[k] = __fdividef(1.f, g_z[beh * Sz + half * 512 + k]);
    __syncthreads();

    const float* p = g_p + ((long long)beh * Sz + half * 512) * Sz + k;
    float acc = 0.f;
#pragma unroll 8
    for (int i = 0; i < 512; i++)
        acc = fmaf(p[(long long)i * Sz], rz[i], acc);
    g_cs[(beh * 2 + half) * Sz + k] = acc;
}

// ---------------------------------------------------------------------------
// Kernel 4: out[b,k,e] = sum over h(4) x half(2) of partial column sums.
// Deterministic (no atomics); writes every output element exactly once.
// ---------------------------------------------------------------------------
__global__ void reduce_out_kernel(float* __restrict__ out)
{
    int t = blockIdx.x * blockDim.x + threadIdx.x;   // 32768 = B*S*E
    if (t >= Bz * Sz * Ez) return;
    int e = t & 7;
    int k = (t >> 3) & 1023;
    int b = t >> 13;
    float s = 0.f;
#pragma unroll
    for (int h = 0; h < NHz; h++) {
        int beh = (b << 5) | (e << 2) | h;
        s += g_cs[(beh * 2 + 0) * Sz + k];
        s += g_cs[(beh * 2 + 1) * Sz + k];
    }
    out[t] = s;
}

// ---------------------------------------------------------------------------
extern "C" void kernel_launch(void* const* d_in, const int* in_sizes, int n_in,
                              void* d_out, int out_size)
{
    const float* x  = (const float*)d_in[0];
    const float* Wq = (const float*)d_in[1];
    const float* bq = (const float*)d_in[2];
    const float* Wk = (const float*)d_in[3];
    const float* bk = (const float*)d_in[4];

    cudaFuncSetAttribute(attn_score_kernel,
                         cudaFuncAttributeMaxDynamicSharedMemorySize, SMEM_B_BYTES);

    dim3 ggrid(NCOLz / 128, (Bz * Sz) / 128);            // (16, 32)
    gemm_qk_kernel<<<ggrid, 256>>>(x, Wq, bq, 0);
    gemm_qk_kernel<<<ggrid, 256>>>(x, Wk, bk, 1);
    attn_score_kernel<<<dim3(BEHz, Sz / 128), 256, SMEM_B_BYTES>>>();
    attn_colsum_kernel<<<dim3(BEHz, 2), 1024>>>();
    reduce_out_kernel<<<(Bz * Sz * Ez + 255) / 256, 256>>>((float*)d_out);
}

// round 2
// speedup vs baseline: 2.6151x; 2.6151x over previous
#include <cuda_runtime.h>
#include <cstdint>

#define Bz   4
#define Sz   1024
#define DINz 1024
#define HDz  64
#define Ez   8
#define NHz  4
#define NCOLz 2048          // HD*E*NH
#define BEHz  128           // B*E*NH

// Scratch (device globals: allocation-free rule)
__device__ float g_qt[BEHz * Sz * HDz];          // [beh][i][d]   32 MB
__device__ float g_kt[BEHz * Sz * HDz];          // [beh][k][d]   32 MB
__device__ float g_cs[BEHz * 8 * Sz];            // [beh][ichunk][k] partial col sums, 4 MB

// ---------------- PTX helpers ----------------
__device__ __forceinline__ void cp16(uint32_t saddr, const void* gptr) {
    asm volatile("cp.async.cg.shared.global [%0], [%1], 16;\n" :: "r"(saddr), "l"(gptr));
}
#define CP_COMMIT() asm volatile("cp.async.commit_group;\n")
#define CP_WAIT(n)  asm volatile("cp.async.wait_group %0;\n" :: "n"(n))

__device__ __forceinline__ void mma_tf32(float* c, const uint32_t* a, const uint32_t* b) {
    asm volatile(
        "mma.sync.aligned.m16n8k8.row.col.f32.tf32.tf32.f32 "
        "{%0,%1,%2,%3}, {%4,%5,%6,%7}, {%8,%9}, {%0,%1,%2,%3};\n"
        : "+f"(c[0]), "+f"(c[1]), "+f"(c[2]), "+f"(c[3])
        : "r"(a[0]), "r"(a[1]), "r"(a[2]), "r"(a[3]), "r"(b[0]), "r"(b[1]));
}

// ---------------------------------------------------------------------------
// Kernel 1: C = X(4096x1024) @ W(1024x2048) + bias, tf32 tensor cores,
// scattered to [beh][i][d].  BM=BN=128, BK=16, 2-stage cp.async pipeline.
// 8 warps: warp grid 2(m) x 4(n), warp tile 64x32, mma m16n8k8.
// ---------------------------------------------------------------------------
#define G_AS 20    // As stride ([m][k]), (20*m + k) % 32 distinct for m0..7,k0..3
#define G_BS 136   // Bs stride ([k][n]), (136*k + n) % 32 = 8k+n distinct

__global__ __launch_bounds__(256)
void gemm_qk_kernel(const float* __restrict__ X, const float* __restrict__ W,
                    const float* __restrict__ bias, int which)
{
    float* __restrict__ out = which ? g_kt : g_qt;
    __shared__ float As[2][128 * G_AS];   // [stage][m*20 + k]
    __shared__ float Bs[2][16 * G_BS];    // [stage][k*136 + n]

    const int bm = blockIdx.y * 128;
    const int bn = blockIdx.x * 128;
    const int tid = threadIdx.x;
    const int w   = tid >> 5;
    const int lane = tid & 31;
    const int wm = w >> 2;           // 0..1
    const int wn = w & 3;            // 0..3
    const int g   = lane >> 2;       // group id 0..7
    const int tig = lane & 3;        // thread in group

    float acc[4][4][4];
#pragma unroll
    for (int mt = 0; mt < 4; mt++)
#pragma unroll
        for (int nt = 0; nt < 4; nt++)
#pragma unroll
            for (int c = 0; c < 4; c++) acc[mt][nt][c] = 0.f;

    // load helper indices
    const int afr = tid >> 2;                 // A: flat float4 idx tid, tid+256
    const int afk = (tid & 3) * 4;
    const int bfr = tid >> 5;                 // B row (k) for f=tid
    const int bfn = (tid & 31) * 4;

    auto load_stage = [&](int s, int k0) {
        // A: 128x16 floats = 512 float4, 2 per thread
        {
            uint32_t d0 = __cvta_generic_to_shared(&As[s][afr * G_AS + afk]);
            cp16(d0, X + (long long)(bm + afr) * DINz + k0 + afk);
            uint32_t d1 = __cvta_generic_to_shared(&As[s][(afr + 64) * G_AS + afk]);
            cp16(d1, X + (long long)(bm + afr + 64) * DINz + k0 + afk);
        }
        // B: 16x128 floats = 512 float4, 2 per thread
        {
            uint32_t d0 = __cvta_generic_to_shared(&Bs[s][bfr * G_BS + bfn]);
            cp16(d0, W + (long long)(k0 + bfr) * NCOLz + bn + bfn);
            uint32_t d1 = __cvta_generic_to_shared(&Bs[s][(bfr + 8) * G_BS + bfn]);
            cp16(d1, W + (long long)(k0 + bfr + 8) * NCOLz + bn + bfn);
        }
    };

    load_stage(0, 0);
    CP_COMMIT();

    const int NIT = DINz / 16;   // 64
    for (int it = 0; it < NIT; it++) {
        int cur = it & 1;
        if (it + 1 < NIT) {
            load_stage(cur ^ 1, (it + 1) * 16);
            CP_COMMIT();
            CP_WAIT(1);
        } else {
            CP_WAIT(0);
        }
        __syncthreads();

        const uint32_t* Asu = (const uint32_t*)As[cur];
        const uint32_t* Bsu = (const uint32_t*)Bs[cur];
#pragma unroll
        for (int s8 = 0; s8 < 2; s8++) {
            int kb = s8 * 8;
            uint32_t afrag[4][4];
#pragma unroll
            for (int mt = 0; mt < 4; mt++) {
                int bi = wm * 64 + mt * 16 + g;
                afrag[mt][0] = Asu[bi * G_AS + kb + tig];
                afrag[mt][1] = Asu[(bi + 8) * G_AS + kb + tig];
                afrag[mt][2] = Asu[bi * G_AS + kb + tig + 4];
                afrag[mt][3] = Asu[(bi + 8) * G_AS + kb + tig + 4];
            }
            uint32_t bfrag[4][2];
#pragma unroll
            for (int nt = 0; nt < 4; nt++) {
                int nb = wn * 32 + nt * 8 + g;
                bfrag[nt][0] = Bsu[(kb + tig) * G_BS + nb];
                bfrag[nt][1] = Bsu[(kb + tig + 4) * G_BS + nb];
            }
#pragma unroll
            for (int mt = 0; mt < 4; mt++)
#pragma unroll
                for (int nt = 0; nt < 4; nt++)
                    mma_tf32(acc[mt][nt], afrag[mt], bfrag[nt]);
        }
        __syncthreads();
    }

    // Epilogue: bias add + scatter to [beh][i][d]; col = d*32 + e*4 + h
#pragma unroll
    for (int mt = 0; mt < 4; mt++) {
#pragma unroll
        for (int nt = 0; nt < 4; nt++) {
#pragma unroll
            for (int c = 0; c < 4; c++) {
                int row = bm + wm * 64 + mt * 16 + g + (c >= 2 ? 8 : 0);
                int col = bn + wn * 32 + nt * 8 + tig * 2 + (c & 1);
                float v = acc[mt][nt][c] + __ldg(bias + col);
                int d = col >> 5, eh = col & 31;
                int bb = row >> 10, si = row & 1023;
                out[((((bb << 5) | eh) * Sz + si) << 6) + d] = v;
            }
        }
    }
}

// ---------------------------------------------------------------------------
// Kernel 2 (fused): per (beh, 128-row ichunk):
//   pass 1: S = QK^T/8 over d=64 (tf32 mma), P=exp(S), row sums Z
//   pass 2: recompute P, weight by 1/Z, column-sum -> g_cs[beh][ichunk][k]
// No P materialization. Warp grid 2(m) x 4(n), warp tile 64x32.
// ---------------------------------------------------------------------------
#define S_QS 68    // Q/K smem stride: (68*i + d) % 32 = 4i+d distinct
#define SC_QS_OFF   0
#define SC_KS_OFF   (128 * S_QS)                 // 8704
#define SC_ZP_OFF   (SC_KS_OFF + 128 * S_QS)     // 17408
#define SC_CP_OFF   (SC_ZP_OFF + 4 * 128)        // 17920
#define SC_RZ_OFF   (SC_CP_OFF + 2 * 128)        // 18176
#define SC_TOTALF   (SC_RZ_OFF + 128)            // 18304 floats
#define SC_SMEM_BYTES (SC_TOTALF * 4)            // 73216

__global__ __launch_bounds__(256)
void attn_score_kernel()
{
    extern __shared__ float sm[];
    float* Qs    = sm + SC_QS_OFF;
    float* Ks    = sm + SC_KS_OFF;
    float* zpart = sm + SC_ZP_OFF;
    float* cpart = sm + SC_CP_OFF;
    float* rz    = sm + SC_RZ_OFF;

    const int beh = blockIdx.x;
    const int ic  = blockIdx.y;
    const int tid = threadIdx.x;
    const int w    = tid >> 5;
    const int lane = tid & 31;
    const int wm = w >> 2;
    const int wn = w & 3;
    const int g   = lane >> 2;
    const int tig = lane & 3;

    const float* qbase = g_qt + ((long long)beh * Sz + ic * 128) * HDz;
    const float* kbase = g_kt + (long long)beh * Sz * HDz;

    // load Q tile 128x64 (float4)
#pragma unroll
    for (int j = 0; j < 8; j++) {
        int f = tid + 256 * j;
        int row = f >> 4, d4 = (f & 15) * 4;
        *(float4*)&Qs[row * S_QS + d4] = *(const float4*)(qbase + row * HDz + d4);
    }

    const uint32_t* Qsu = (const uint32_t*)Qs;
    const uint32_t* Ksu = (const uint32_t*)Ks;

    float acc[4][4][4];

    // common compute of one 128x128 S tile (for current Ks contents)
    auto compute_tile = [&]() {
#pragma unroll
        for (int mt = 0; mt < 4; mt++)
#pragma unroll
            for (int nt = 0; nt < 4; nt++)
#pragma unroll
                for (int c = 0; c < 4; c++) acc[mt][nt][c] = 0.f;
#pragma unroll
        for (int d8 = 0; d8 < 8; d8++) {
            int kb = d8 * 8;
            uint32_t afrag[4][4];
#pragma unroll
            for (int mt = 0; mt < 4; mt++) {
                int bi = wm * 64 + mt * 16 + g;
                afrag[mt][0] = Qsu[bi * S_QS + kb + tig];
                afrag[mt][1] = Qsu[(bi + 8) * S_QS + kb + tig];
                afrag[mt][2] = Qsu[bi * S_QS + kb + tig + 4];
                afrag[mt][3] = Qsu[(bi + 8) * S_QS + kb + tig + 4];
            }
            uint32_t bfrag[4][2];
#pragma unroll
            for (int nt = 0; nt < 4; nt++) {
                int nb = wn * 32 + nt * 8 + g;
                bfrag[nt][0] = Ksu[nb * S_QS + kb + tig];
                bfrag[nt][1] = Ksu[nb * S_QS + kb + tig + 4];
            }
#pragma unroll
            for (int mt = 0; mt < 4; mt++)
#pragma unroll
                for (int nt = 0; nt < 4; nt++)
                    mma_tf32(acc[mt][nt], afrag[mt], bfrag[nt]);
        }
    };

    auto load_k = [&](int kc) {
#pragma unroll
        for (int j = 0; j < 8; j++) {
            int f = tid + 256 * j;
            int row = f >> 4, d4 = (f & 15) * 4;
            *(float4*)&Ks[row * S_QS + d4] =
                *(const float4*)(kbase + (kc * 128 + row) * HDz + d4);
        }
    };

    // ---------------- PASS 1: row sums Z ----------------
    float zacc[4][2];
#pragma unroll
    for (int mt = 0; mt < 4; mt++) { zacc[mt][0] = 0.f; zacc[mt][1] = 0.f; }

    for (int kc = 0; kc < 8; kc++) {
        __syncthreads();
        load_k(kc);
        __syncthreads();
        compute_tile();
#pragma unroll
        for (int mt = 0; mt < 4; mt++)
#pragma unroll
            for (int nt = 0; nt < 4; nt++) {
                zacc[mt][0] += __expf(acc[mt][nt][0] * 0.125f)
                             + __expf(acc[mt][nt][1] * 0.125f);
                zacc[mt][1] += __expf(acc[mt][nt][2] * 0.125f)
                             + __expf(acc[mt][nt][3] * 0.125f);
            }
    }

    // reduce Z: over tig (cols within warp), then over wn warps via smem
#pragma unroll
    for (int mt = 0; mt < 4; mt++) {
        float z0 = zacc[mt][0], z1 = zacc[mt][1];
        z0 += __shfl_xor_sync(0xffffffffu, z0, 1);
        z0 += __shfl_xor_sync(0xffffffffu, z0, 2);
        z1 += __shfl_xor_sync(0xffffffffu, z1, 1);
        z1 += __shfl_xor_sync(0xffffffffu, z1, 2);
        if (tig == 0) {
            int r = wm * 64 + mt * 16 + g;
            zpart[wn * 128 + r]     = z0;
            zpart[wn * 128 + r + 8] = z1;
        }
    }
    __syncthreads();
    if (tid < 128) {
        float z = zpart[tid] + zpart[128 + tid] + zpart[256 + tid] + zpart[384 + tid];
        rz[tid] = __fdividef(1.f, z);
    }

    // ---------------- PASS 2: weighted column sums ----------------
    float* csout = g_cs + ((long long)(beh * 8 + ic)) * Sz;
    for (int kc = 0; kc < 8; kc++) {
        __syncthreads();            // also guards rz visibility on first iter
        load_k(kc);
        __syncthreads();
        compute_tile();

        float colacc[4][2];
#pragma unroll
        for (int nt = 0; nt < 4; nt++) { colacc[nt][0] = 0.f; colacc[nt][1] = 0.f; }
#pragma unroll
        for (int mt = 0; mt < 4; mt++) {
            int r = wm * 64 + mt * 16 + g;
            float r0 = rz[r], r1 = rz[r + 8];
#pragma unroll
            for (int nt = 0; nt < 4; nt++) {
                colacc[nt][0] += __expf(acc[mt][nt][0] * 0.125f) * r0
                               + __expf(acc[mt][nt][2] * 0.125f) * r1;
                colacc[nt][1] += __expf(acc[mt][nt][1] * 0.125f) * r0
                               + __expf(acc[mt][nt][3] * 0.125f) * r1;
            }
        }
        // reduce over g (8 row-groups): lanes differ in bits 2..4
#pragma unroll
        for (int nt = 0; nt < 4; nt++) {
#pragma unroll
            for (int c = 0; c < 2; c++) {
                float v = colacc[nt][c];
                v += __shfl_xor_sync(0xffffffffu, v, 4);
                v += __shfl_xor_sync(0xffffffffu, v, 8);
                v += __shfl_xor_sync(0xffffffffu, v, 16);
                colacc[nt][c] = v;
            }
        }
        if (g == 0) {
#pragma unroll
            for (int nt = 0; nt < 4; nt++) {
                cpart[wm * 128 + wn * 32 + nt * 8 + tig * 2]     = colacc[nt][0];
                cpart[wm * 128 + wn * 32 + nt * 8 + tig * 2 + 1] = colacc[nt][1];
            }
        }
        __syncthreads();
        if (tid < 128)
            csout[kc * 128 + tid] = cpart[tid] + cpart[128 + tid];
        // next iteration's leading __syncthreads() guards cpart reuse
    }
}

// ---------------------------------------------------------------------------
// Kernel 3: out[b,k,e] = sum over h(4) x ichunk(8) of partial column sums.
// ---------------------------------------------------------------------------
__global__ __launch_bounds__(256)
void reduce_out_kernel(float* __restrict__ out)
{
    int t = blockIdx.x * blockDim.x + threadIdx.x;   // 32768 = B*S*E
    if (t >= Bz * Sz * Ez) return;
    int k = t & 1023;
    int e = (t >> 10) & 7;
    int b = t >> 13;
    float s = 0.f;
#pragma unroll
    for (int h = 0; h < NHz; h++) {
        int beh = (b << 5) | (e << 2) | h;
        const float* base = g_cs + (long long)beh * 8 * Sz + k;
#pragma unroll
        for (int icu = 0; icu < 8; icu++)
            s += base[icu * Sz];
    }
    out[((b << 10) | k) * Ez + e] = s;
}

// ---------------------------------------------------------------------------
extern "C" void kernel_launch(void* const* d_in, const int* in_sizes, int n_in,
                              void* d_out, int out_size)
{
    const float* x  = (const float*)d_in[0];
    const float* Wq = (const float*)d_in[1];
    const float* bq = (const float*)d_in[2];
    const float* Wk = (const float*)d_in[3];
    const float* bk = (const float*)d_in[4];

    cudaFuncSetAttribute(attn_score_kernel,
                         cudaFuncAttributeMaxDynamicSharedMemorySize, SC_SMEM_BYTES);

    dim3 ggrid(NCOLz / 128, (Bz * Sz) / 128);            // (16, 32)
    gemm_qk_kernel<<<ggrid, 256>>>(x, Wq, bq, 0);
    gemm_qk_kernel<<<ggrid, 256>>>(x, Wk, bk, 1);
    attn_score_kernel<<<dim3(BEHz, Sz / 128), 256, SC_SMEM_BYTES>>>();
    reduce_out_kernel<<<(Bz * Sz * Ez + 255) / 256, 256>>>((float*)d_out);
}